// round 1
// baseline (speedup 1.0000x reference)
#include <cuda_runtime.h>
#include <math.h>

// ---------------- problem constants ----------------
#define BWIN   2048        // windows*batch
#define NTOK   64          // tokens per window
#define CHANS  512
#define NHEAD  16
#define HDIM   32
#define NWMASK 256
#define MROWS  (BWIN * NTOK)     // 131072
#define QKVN   (3 * CHANS)       // 1536
#define LOGMAX 4.6051701859880914f   // ln(100)

// ---------------- scratch (static device allocations are allowed) --------
__device__ float g_qkv[(size_t)MROWS * QKVN];        // 805 MB
__device__ float g_attn_out[(size_t)MROWS * CHANS];  // 268 MB
__device__ float g_table[225 * NHEAD];
__device__ float g_bias[NHEAD * NTOK * NTOK];
__device__ float g_qkv_bias[QKVN];

// ---------------- tiny prep kernels ----------------
__global__ void qkvbias_kernel(const float* __restrict__ qb,
                               const float* __restrict__ vb) {
    int n = blockIdx.x * 256 + threadIdx.x;
    if (n >= QKVN) return;
    float v = 0.f;
    if (n < CHANS) v = qb[n];
    else if (n >= 2 * CHANS) v = vb[n - 2 * CHANS];
    g_qkv_bias[n] = v;
}

// CPB MLP: table[p][h] = (relu(rel[p]@W1 + b1) @ W2)[h],  p in [0,225)
__global__ void cpb_table_kernel(const float* __restrict__ rel_table,
                                 const float* __restrict__ w1,
                                 const float* __restrict__ b1,
                                 const float* __restrict__ w2) {
    int p = blockIdx.x;          // 225
    int j = threadIdx.x;         // 512
    __shared__ float hid[512];
    float t0 = rel_table[p * 2 + 0];
    float t1 = rel_table[p * 2 + 1];
    hid[j] = fmaxf(t0 * w1[j] + t1 * w1[512 + j] + b1[j], 0.f);
    __syncthreads();
    if (j < NHEAD) {
        float acc = 0.f;
        #pragma unroll 8
        for (int r = 0; r < 512; ++r) acc += hid[r] * w2[r * NHEAD + j];
        g_table[p * NHEAD + j] = acc;
    }
}

// bias[h][i][j] = 16*sigmoid(table[idx(i,j)][h])
__global__ void bias_expand_kernel() {
    int id = blockIdx.x * 256 + threadIdx.x;   // 65536
    int h = id >> 12;
    int i = (id >> 6) & 63;
    int j = id & 63;
    int idx = ((i >> 3) - (j >> 3) + 7) * 15 + ((i & 7) - (j & 7) + 7);
    float b = g_table[idx * NHEAD + h];
    g_bias[id] = 16.f / (1.f + __expf(-b));
}

// ---------------- fp32 SGEMM: C[M,N] = A[M,K] @ B[K,N] + bias[N] ----------
// BM=128 BN=128 BK=16, 256 threads, 8x8 per thread. M%128==N%128==K%16==0.
__global__ __launch_bounds__(256)
void sgemm_bias(const float* __restrict__ A, const float* __restrict__ Bm,
                const float* __restrict__ bias, float* __restrict__ C,
                int M, int N, int K) {
    __shared__ float As[16][128];
    __shared__ float Bs[16][128];
    const int tid = threadIdx.x;
    const int bm = blockIdx.y * 128;
    const int bn = blockIdx.x * 128;
    const int tx = tid & 15;          // col group
    const int ty = tid >> 4;          // row group
    float acc[8][8] = {};
    float areg[8], breg[8];

    for (int k0 = 0; k0 < K; k0 += 16) {
        #pragma unroll
        for (int l = 0; l < 2; ++l) {
            int t = tid + l * 256;
            // A tile: 128 rows x 16 cols -> As transposed [k][m]
            int ar = t >> 2;
            int ac = (t & 3) << 2;
            float4 av = *(const float4*)&A[(size_t)(bm + ar) * K + k0 + ac];
            As[ac + 0][ar] = av.x;
            As[ac + 1][ar] = av.y;
            As[ac + 2][ar] = av.z;
            As[ac + 3][ar] = av.w;
            // B tile: 16 rows x 128 cols
            int br = t >> 5;
            int bc = (t & 31) << 2;
            *(float4*)&Bs[br][bc] = *(const float4*)&Bm[(size_t)(k0 + br) * N + bn + bc];
        }
        __syncthreads();
        #pragma unroll
        for (int kk = 0; kk < 16; ++kk) {
            #pragma unroll
            for (int i = 0; i < 8; i += 4) *(float4*)&areg[i] = *(float4*)&As[kk][ty * 8 + i];
            #pragma unroll
            for (int j = 0; j < 8; j += 4) *(float4*)&breg[j] = *(float4*)&Bs[kk][tx * 8 + j];
            #pragma unroll
            for (int i = 0; i < 8; ++i)
                #pragma unroll
                for (int j = 0; j < 8; ++j)
                    acc[i][j] += areg[i] * breg[j];
        }
        __syncthreads();
    }
    #pragma unroll
    for (int i = 0; i < 8; ++i) {
        size_t row = (size_t)(bm + ty * 8 + i) * N;
        #pragma unroll
        for (int j = 0; j < 8; j += 4) {
            int col = bn + tx * 8 + j;
            float4 o;
            o.x = acc[i][j + 0] + bias[col + 0];
            o.y = acc[i][j + 1] + bias[col + 1];
            o.z = acc[i][j + 2] + bias[col + 2];
            o.w = acc[i][j + 3] + bias[col + 3];
            *(float4*)&C[row + col] = o;
        }
    }
}

// ---------------- attention: one CTA per (head, window) ------------------
__global__ __launch_bounds__(256)
void attn_kernel(const float* __restrict__ mask,
                 const float* __restrict__ logit_scale) {
    const int h = blockIdx.x;     // 16
    const int win = blockIdx.y;   // 2048
    __shared__ float qs[64][32];
    __shared__ float ks[64][32];
    __shared__ float vs[64][32];
    __shared__ float S[64][65];
    const int tid = threadIdx.x;  // 256

    // load q,k,v for this (window, head): rows are (win*64+n), q/k/v at col
    // offsets h*32, 512+h*32, 1024+h*32 of the 1536-wide qkv row.
    const size_t base = (size_t)win * 64 * QKVN + h * HDIM;
    #pragma unroll
    for (int l = 0; l < 2; ++l) {
        int t = tid + l * 256;
        int n = t >> 3;
        int f = (t & 7) << 2;
        const float* rowp = &g_qkv[base + (size_t)n * QKVN];
        *(float4*)&qs[n][f] = *(const float4*)&rowp[f];
        *(float4*)&ks[n][f] = *(const float4*)&rowp[512 + f];
        *(float4*)&vs[n][f] = *(const float4*)&rowp[1024 + f];
    }
    __syncthreads();

    // L2-normalize q and k rows (one thread per row)
    if (tid < 128) {
        int r = tid & 63;
        float* row = (tid < 64) ? qs[r] : ks[r];
        float ss = 0.f;
        #pragma unroll
        for (int d4 = 0; d4 < 32; d4 += 4) {
            float4 v = *(float4*)&row[d4];
            ss += v.x * v.x + v.y * v.y + v.z * v.z + v.w * v.w;
        }
        float inv = rsqrtf(ss);
        #pragma unroll
        for (int d = 0; d < 32; ++d) row[d] *= inv;
    }
    float scale = __expf(fminf(logit_scale[h], LOGMAX));
    __syncthreads();

    // S[i][j] = qn_i . kn_j * scale + bias[h][i][j] + mask[win%256][i][j]
    const int i = tid >> 2;
    const int j0 = (tid & 3) * 16;
    float q[32];
    #pragma unroll
    for (int d = 0; d < 32; ++d) q[d] = qs[i][d];
    const float* bias_h = &g_bias[h * 4096];
    const float* mask_w = &mask[(size_t)(win & (NWMASK - 1)) * 4096];
    #pragma unroll
    for (int j = j0; j < j0 + 16; ++j) {
        float s = 0.f;
        #pragma unroll
        for (int d = 0; d < 32; ++d) s += q[d] * ks[j][d];
        S[i][j] = s * scale + bias_h[i * 64 + j] + mask_w[i * 64 + j];
    }
    __syncthreads();

    // softmax over rows (one thread per row)
    if (tid < 64) {
        float m = -1e30f;
        #pragma unroll
        for (int j = 0; j < 64; ++j) m = fmaxf(m, S[tid][j]);
        float sum = 0.f;
        #pragma unroll
        for (int j = 0; j < 64; ++j) {
            float e = __expf(S[tid][j] - m);
            S[tid][j] = e;
            sum += e;
        }
        float inv = 1.f / sum;
        #pragma unroll
        for (int j = 0; j < 64; ++j) S[tid][j] *= inv;
    }
    __syncthreads();

    // out[i][:] = P[i][:] @ V ; thread covers 8 of the 32 head dims
    const int dd0 = (tid & 3) * 8;
    float acc[8] = {};
    #pragma unroll
    for (int j = 0; j < 64; ++j) {
        float p = S[i][j];
        #pragma unroll
        for (int u = 0; u < 8; ++u) acc[u] += p * vs[j][dd0 + u];
    }
    size_t orow = ((size_t)win * 64 + i) * CHANS + h * HDIM + dd0;
    *(float4*)&g_attn_out[orow]     = make_float4(acc[0], acc[1], acc[2], acc[3]);
    *(float4*)&g_attn_out[orow + 4] = make_float4(acc[4], acc[5], acc[6], acc[7]);
}

// ---------------- launch ----------------
extern "C" void kernel_launch(void* const* d_in, const int* in_sizes, int n_in,
                              void* d_out, int out_size) {
    const float* x       = (const float*)d_in[0];
    const float* mask    = (const float*)d_in[1];
    const float* rel_t   = (const float*)d_in[2];
    const float* w_qkv   = (const float*)d_in[3];
    const float* q_bias  = (const float*)d_in[4];
    const float* v_bias  = (const float*)d_in[5];
    const float* lscale  = (const float*)d_in[6];
    const float* cpb_w1  = (const float*)d_in[7];
    const float* cpb_b1  = (const float*)d_in[8];
    const float* cpb_w2  = (const float*)d_in[9];
    const float* proj_w  = (const float*)d_in[10];
    const float* proj_b  = (const float*)d_in[11];
    float* out = (float*)d_out;

    void *p_qkv, *p_ao, *p_qb;
    cudaGetSymbolAddress(&p_qkv, g_qkv);
    cudaGetSymbolAddress(&p_ao, g_attn_out);
    cudaGetSymbolAddress(&p_qb, g_qkv_bias);

    qkvbias_kernel<<<6, 256>>>(q_bias, v_bias);
    cpb_table_kernel<<<225, 512>>>(rel_t, cpb_w1, cpb_b1, cpb_w2);
    bias_expand_kernel<<<256, 256>>>();

    // QKV projection: [131072,512] @ [512,1536]
    sgemm_bias<<<dim3(QKVN / 128, MROWS / 128), 256>>>(
        x, w_qkv, (const float*)p_qb, (float*)p_qkv, MROWS, QKVN, CHANS);

    // attention per (head, window)
    attn_kernel<<<dim3(NHEAD, BWIN), 256>>>(mask, lscale);

    // output projection: [131072,512] @ [512,512]
    sgemm_bias<<<dim3(CHANS / 128, MROWS / 128), 256>>>(
        (const float*)p_ao, proj_w, proj_b, out, MROWS, CHANS, CHANS);
}

// round 3
// speedup vs baseline: 1.5254x; 1.5254x over previous
#include <cuda_runtime.h>
#include <cuda_bf16.h>
#include <math.h>
#include <stdint.h>

// ---------------- problem constants ----------------
#define BWIN   2048
#define NTOK   64
#define CHANS  512
#define NHEAD  16
#define HDIM   32
#define NWMASK 256
#define MROWS  (BWIN * NTOK)     // 131072
#define QKVN   (3 * CHANS)       // 1536
#define LOGMAX 4.6051701859880914f

// ---------------- scratch ----------------
__device__ float g_qkv[(size_t)MROWS * QKVN];
__device__ __nv_bfloat16 g_x_hi[(size_t)MROWS * CHANS];
__device__ __nv_bfloat16 g_x_lo[(size_t)MROWS * CHANS];
__device__ __nv_bfloat16 g_ao_hi[(size_t)MROWS * CHANS];
__device__ __nv_bfloat16 g_ao_lo[(size_t)MROWS * CHANS];
__device__ __nv_bfloat16 g_wq_hi[(size_t)QKVN * CHANS];   // [N,K] transposed
__device__ __nv_bfloat16 g_wq_lo[(size_t)QKVN * CHANS];
__device__ __nv_bfloat16 g_wp_hi[(size_t)CHANS * CHANS];
__device__ __nv_bfloat16 g_wp_lo[(size_t)CHANS * CHANS];
__device__ float g_table[225 * NHEAD];
__device__ float g_bias[NHEAD * NTOK * NTOK];
__device__ float g_qkv_bias[QKVN];

// ---------------- helpers ----------------
__device__ __forceinline__ uint32_t smem_u32(const void* p) {
    uint32_t a;
    asm("{ .reg .u64 t; cvta.to.shared.u64 t, %1; cvt.u32.u64 %0, t; }" : "=r"(a) : "l"(p));
    return a;
}
__device__ __forceinline__ void cp16(uint32_t dst, const void* src) {
    asm volatile("cp.async.cg.shared.global [%0], [%1], 16;" :: "r"(dst), "l"(src));
}
#define CP_COMMIT() asm volatile("cp.async.commit_group;" ::: "memory")
__device__ __forceinline__ void cp_wait(int rem) {
    if (rem >= 2)      asm volatile("cp.async.wait_group 2;" ::: "memory");
    else if (rem == 1) asm volatile("cp.async.wait_group 1;" ::: "memory");
    else               asm volatile("cp.async.wait_group 0;" ::: "memory");
}
__device__ __forceinline__ void ldm_x4(uint32_t* r, uint32_t addr) {
    asm volatile("ldmatrix.sync.aligned.m8n8.x4.shared.b16 {%0,%1,%2,%3}, [%4];"
                 : "=r"(r[0]), "=r"(r[1]), "=r"(r[2]), "=r"(r[3]) : "r"(addr));
}
__device__ __forceinline__ void mma_bf16(float* d, const uint32_t* a, uint32_t b0, uint32_t b1) {
    asm volatile(
        "mma.sync.aligned.m16n8k16.row.col.f32.bf16.bf16.f32 "
        "{%0,%1,%2,%3}, {%4,%5,%6,%7}, {%8,%9}, {%0,%1,%2,%3};"
        : "+f"(d[0]), "+f"(d[1]), "+f"(d[2]), "+f"(d[3])
        : "r"(a[0]), "r"(a[1]), "r"(a[2]), "r"(a[3]), "r"(b0), "r"(b1));
}
__device__ __forceinline__ void split1(float x, __nv_bfloat16& h, __nv_bfloat16& l) {
    h = __float2bfloat16(x);
    l = __float2bfloat16(x - __bfloat162float(h));
}

// ---------------- tiny prep kernels ----------------
__global__ void qkvbias_kernel(const float* __restrict__ qb,
                               const float* __restrict__ vb) {
    int n = blockIdx.x * 256 + threadIdx.x;
    if (n >= QKVN) return;
    float v = 0.f;
    if (n < CHANS) v = qb[n];
    else if (n >= 2 * CHANS) v = vb[n - 2 * CHANS];
    g_qkv_bias[n] = v;
}

__global__ void cpb_table_kernel(const float* __restrict__ rel_table,
                                 const float* __restrict__ w1,
                                 const float* __restrict__ b1,
                                 const float* __restrict__ w2) {
    int p = blockIdx.x;
    int j = threadIdx.x;
    __shared__ float hid[512];
    float t0 = rel_table[p * 2 + 0];
    float t1 = rel_table[p * 2 + 1];
    hid[j] = fmaxf(t0 * w1[j] + t1 * w1[512 + j] + b1[j], 0.f);
    __syncthreads();
    if (j < NHEAD) {
        float acc = 0.f;
        #pragma unroll 8
        for (int r = 0; r < 512; ++r) acc += hid[r] * w2[r * NHEAD + j];
        g_table[p * NHEAD + j] = acc;
    }
}

__global__ void bias_expand_kernel() {
    int id = blockIdx.x * 256 + threadIdx.x;
    int h = id >> 12;
    int i = (id >> 6) & 63;
    int j = id & 63;
    int idx = ((i >> 3) - (j >> 3) + 7) * 15 + ((i & 7) - (j & 7) + 7);
    float b = g_table[idx * NHEAD + h];
    g_bias[id] = 16.f / (1.f + __expf(-b));
}

__global__ void split_x_kernel(const float* __restrict__ src) {
    size_t i = ((size_t)blockIdx.x * 256 + threadIdx.x) * 4;
    float4 v = *(const float4*)&src[i];
    __align__(8) __nv_bfloat16 h[4], l[4];
    split1(v.x, h[0], l[0]);
    split1(v.y, h[1], l[1]);
    split1(v.z, h[2], l[2]);
    split1(v.w, h[3], l[3]);
    *(uint2*)&g_x_hi[i] = *(uint2*)h;
    *(uint2*)&g_x_lo[i] = *(uint2*)l;
}

__global__ void wsplit_kernel(const float* __restrict__ w,
                              __nv_bfloat16* __restrict__ hiT,
                              __nv_bfloat16* __restrict__ loT,
                              int K, int N) {
    int idx = blockIdx.x * 256 + threadIdx.x;
    if (idx >= K * N) return;
    int k = idx / N, n = idx % N;
    __nv_bfloat16 h, l;
    split1(w[idx], h, l);
    hiT[(size_t)n * K + k] = h;
    loT[(size_t)n * K + k] = l;
}

// ---------------- HMMA bf16x3 GEMM ----------------
// C[M,N] = (Ahi+Alo)[M,K] @ (Bhi+Blo)[N,K]^T + bias[N]
// BM=128 BN=128 BK=32, 256 thr (8 warps 2Mx4N), warp tile 64x32,
// 3-stage cp.async pipeline, ldmatrix + mma.sync m16n8k16 bf16,
// products: hi*hi + hi*lo + lo*hi.
#define PITCH 40                         // bf16 elems per smem row (80 B)
#define TILE_B (128 * PITCH * 2)         // 10240 B per operand tile
#define STAGE_B (4 * TILE_B)             // Ahi,Alo,Bhi,Blo
#define NSTAGE 3
#define GEMM_SMEM (NSTAGE * STAGE_B)     // 122880 B

__global__ void __launch_bounds__(256)
hmma_gemm(const __nv_bfloat16* __restrict__ Ahi, const __nv_bfloat16* __restrict__ Alo,
          const __nv_bfloat16* __restrict__ Bhi, const __nv_bfloat16* __restrict__ Blo,
          const float* __restrict__ bias, float* __restrict__ C,
          int M, int N, int K) {
    extern __shared__ char smem[];
    const uint32_t sb = smem_u32(smem);
    const int tid = threadIdx.x;
    const int wid = tid >> 5, lane = tid & 31;
    const int bm = blockIdx.y * 128;
    const int bn = blockIdx.x * 128;
    const int wm = (wid >> 2) * 64;      // warp row offset
    const int wn = (wid & 3) * 32;       // warp col offset
    const int nch = K >> 5;

    // cp.async loader: one operand tile (128 rows x 32 cols)
    auto load_tile = [&](const __nv_bfloat16* g, int rowbase, int k0, uint32_t off) {
        #pragma unroll
        for (int c = tid; c < 512; c += 256) {
            int row = c >> 2, chunk = c & 3;
            cp16(sb + off + row * (PITCH * 2) + chunk * 16,
                 g + (size_t)(rowbase + row) * K + k0 + chunk * 8);
        }
    };
    auto load_chunk = [&](int chunk) {
        int k0 = chunk << 5;
        uint32_t s0 = (uint32_t)(chunk % NSTAGE) * STAGE_B;
        load_tile(Ahi, bm, k0, s0);
        load_tile(Alo, bm, k0, s0 + TILE_B);
        load_tile(Bhi, bn, k0, s0 + 2 * TILE_B);
        load_tile(Blo, bn, k0, s0 + 3 * TILE_B);
        CP_COMMIT();
    };

    float acc[4][4][4] = {};   // [mi][nj][reg]

    load_chunk(0);
    if (nch > 1) load_chunk(1);

    // ldmatrix lane address components
    const int lt = lane >> 3;            // tile id 0..3
    const int lr = lane & 7;             // row in tile
    // A: row = (tile&1)*8 + lr ; k16 chunk = tile>>1
    const int a_row_in = ((lt & 1) << 3) + lr;
    const int a_k16 = lt >> 1;
    // B: n = (tile>>1)*8 + lr ; k16 chunk = tile&1
    const int b_n_in = ((lt >> 1) << 3) + lr;
    const int b_k16 = lt & 1;

    for (int i = 0; i < nch; ++i) {
        if (i + 2 < nch) load_chunk(i + 2);
        cp_wait(nch - 1 - i);
        __syncthreads();

        const uint32_t s0 = sb + (uint32_t)(i % NSTAGE) * STAGE_B;
        #pragma unroll
        for (int ks = 0; ks < 2; ++ks) {
            uint32_t afh[4][4], bfh[2][4], tf[4][4];
            // A hi frags (m64)
            #pragma unroll
            for (int mi = 0; mi < 4; ++mi)
                ldm_x4(afh[mi], s0 + (wm + mi * 16 + a_row_in) * (PITCH * 2)
                                 + ks * 32 + a_k16 * 16);
            // B hi frags (n32)
            #pragma unroll
            for (int ni = 0; ni < 2; ++ni)
                ldm_x4(bfh[ni], s0 + 2 * TILE_B
                                 + (wn + ni * 16 + b_n_in) * (PITCH * 2)
                                 + ks * 32 + b_k16 * 16);
            // hi*hi
            #pragma unroll
            for (int mi = 0; mi < 4; ++mi)
                #pragma unroll
                for (int nj = 0; nj < 4; ++nj)
                    mma_bf16(acc[mi][nj], afh[mi], bfh[nj >> 1][(nj & 1) * 2],
                             bfh[nj >> 1][(nj & 1) * 2 + 1]);
            // B lo frags -> hi*lo
            #pragma unroll
            for (int ni = 0; ni < 2; ++ni)
                ldm_x4(tf[ni], s0 + 3 * TILE_B
                                + (wn + ni * 16 + b_n_in) * (PITCH * 2)
                                + ks * 32 + b_k16 * 16);
            #pragma unroll
            for (int mi = 0; mi < 4; ++mi)
                #pragma unroll
                for (int nj = 0; nj < 4; ++nj)
                    mma_bf16(acc[mi][nj], afh[mi], tf[nj >> 1][(nj & 1) * 2],
                             tf[nj >> 1][(nj & 1) * 2 + 1]);
            // A lo frags -> lo*hi
            #pragma unroll
            for (int mi = 0; mi < 4; ++mi)
                ldm_x4(tf[mi], s0 + TILE_B + (wm + mi * 16 + a_row_in) * (PITCH * 2)
                                + ks * 32 + a_k16 * 16);
            #pragma unroll
            for (int mi = 0; mi < 4; ++mi)
                #pragma unroll
                for (int nj = 0; nj < 4; ++nj)
                    mma_bf16(acc[mi][nj], tf[mi], bfh[nj >> 1][(nj & 1) * 2],
                             bfh[nj >> 1][(nj & 1) * 2 + 1]);
        }
        __syncthreads();
    }

    // epilogue: regs -> global with bias
    const int er = lane >> 2;            // 0..7
    const int ec = (lane & 3) * 2;       // 0,2,4,6
    #pragma unroll
    for (int mi = 0; mi < 4; ++mi) {
        #pragma unroll
        for (int nj = 0; nj < 4; ++nj) {
            int col = bn + wn + nj * 8 + ec;
            float b0 = bias[col], b1 = bias[col + 1];
            int r0 = bm + wm + mi * 16 + er;
            float2 v0 = make_float2(acc[mi][nj][0] + b0, acc[mi][nj][1] + b1);
            float2 v1 = make_float2(acc[mi][nj][2] + b0, acc[mi][nj][3] + b1);
            *(float2*)&C[(size_t)r0 * N + col] = v0;
            *(float2*)&C[(size_t)(r0 + 8) * N + col] = v1;
        }
    }
}

// ---------------- attention: one CTA per (head, window) ------------------
__global__ __launch_bounds__(256)
void attn_kernel(const float* __restrict__ mask,
                 const float* __restrict__ logit_scale) {
    const int h = blockIdx.x;
    const int win = blockIdx.y;
    __shared__ float qs[64][32];
    __shared__ float ks[64][32];
    __shared__ float vs[64][32];
    __shared__ float S[64][65];
    const int tid = threadIdx.x;

    const size_t base = (size_t)win * 64 * QKVN + h * HDIM;
    #pragma unroll
    for (int l = 0; l < 2; ++l) {
        int t = tid + l * 256;
        int n = t >> 3;
        int f = (t & 7) << 2;
        const float* rowp = &g_qkv[base + (size_t)n * QKVN];
        *(float4*)&qs[n][f] = *(const float4*)&rowp[f];
        *(float4*)&ks[n][f] = *(const float4*)&rowp[512 + f];
        *(float4*)&vs[n][f] = *(const float4*)&rowp[1024 + f];
    }
    __syncthreads();

    if (tid < 128) {
        int r = tid & 63;
        float* row = (tid < 64) ? qs[r] : ks[r];
        float ss = 0.f;
        #pragma unroll
        for (int d4 = 0; d4 < 32; d4 += 4) {
            float4 v = *(float4*)&row[d4];
            ss += v.x * v.x + v.y * v.y + v.z * v.z + v.w * v.w;
        }
        float inv = rsqrtf(ss);
        #pragma unroll
        for (int d = 0; d < 32; ++d) row[d] *= inv;
    }
    float scale = __expf(fminf(logit_scale[h], LOGMAX));
    __syncthreads();

    const int i = tid >> 2;
    const int j0 = (tid & 3) * 16;
    float q[32];
    #pragma unroll
    for (int d = 0; d < 32; ++d) q[d] = qs[i][d];
    const float* bias_h = &g_bias[h * 4096];
    const float* mask_w = &mask[(size_t)(win & (NWMASK - 1)) * 4096];
    #pragma unroll
    for (int j = j0; j < j0 + 16; ++j) {
        float s = 0.f;
        #pragma unroll
        for (int d = 0; d < 32; ++d) s += q[d] * ks[j][d];
        S[i][j] = s * scale + bias_h[i * 64 + j] + mask_w[i * 64 + j];
    }
    __syncthreads();

    if (tid < 64) {
        float m = -1e30f;
        #pragma unroll
        for (int j = 0; j < 64; ++j) m = fmaxf(m, S[tid][j]);
        float sum = 0.f;
        #pragma unroll
        for (int j = 0; j < 64; ++j) {
            float e = __expf(S[tid][j] - m);
            S[tid][j] = e;
            sum += e;
        }
        float inv = 1.f / sum;
        #pragma unroll
        for (int j = 0; j < 64; ++j) S[tid][j] *= inv;
    }
    __syncthreads();

    const int dd0 = (tid & 3) * 8;
    float acc[8] = {};
    #pragma unroll
    for (int j = 0; j < 64; ++j) {
        float p = S[i][j];
        #pragma unroll
        for (int u = 0; u < 8; ++u) acc[u] += p * vs[j][dd0 + u];
    }
    size_t orow = ((size_t)win * 64 + i) * CHANS + h * HDIM + dd0;
    __align__(16) __nv_bfloat16 hv[8], lv[8];
    #pragma unroll
    for (int u = 0; u < 8; ++u) split1(acc[u], hv[u], lv[u]);
    *(uint4*)&g_ao_hi[orow] = *(uint4*)hv;
    *(uint4*)&g_ao_lo[orow] = *(uint4*)lv;
}

// ---------------- launch ----------------
extern "C" void kernel_launch(void* const* d_in, const int* in_sizes, int n_in,
                              void* d_out, int out_size) {
    const float* x       = (const float*)d_in[0];
    const float* mask    = (const float*)d_in[1];
    const float* rel_t   = (const float*)d_in[2];
    const float* w_qkv   = (const float*)d_in[3];
    const float* q_bias  = (const float*)d_in[4];
    const float* v_bias  = (const float*)d_in[5];
    const float* lscale  = (const float*)d_in[6];
    const float* cpb_w1  = (const float*)d_in[7];
    const float* cpb_b1  = (const float*)d_in[8];
    const float* cpb_w2  = (const float*)d_in[9];
    const float* proj_w  = (const float*)d_in[10];
    const float* proj_b  = (const float*)d_in[11];
    float* out = (float*)d_out;

    void *p_qkv, *p_qb, *p_xh, *p_xl, *p_aoh, *p_aol, *p_wqh, *p_wql, *p_wph, *p_wpl;
    cudaGetSymbolAddress(&p_qkv, g_qkv);
    cudaGetSymbolAddress(&p_qb, g_qkv_bias);
    cudaGetSymbolAddress(&p_xh, g_x_hi);
    cudaGetSymbolAddress(&p_xl, g_x_lo);
    cudaGetSymbolAddress(&p_aoh, g_ao_hi);
    cudaGetSymbolAddress(&p_aol, g_ao_lo);
    cudaGetSymbolAddress(&p_wqh, g_wq_hi);
    cudaGetSymbolAddress(&p_wql, g_wq_lo);
    cudaGetSymbolAddress(&p_wph, g_wp_hi);
    cudaGetSymbolAddress(&p_wpl, g_wp_lo);

    cudaFuncSetAttribute(hmma_gemm, cudaFuncAttributeMaxDynamicSharedMemorySize, GEMM_SMEM);

    qkvbias_kernel<<<6, 256>>>(q_bias, v_bias);
    cpb_table_kernel<<<225, 512>>>(rel_t, cpb_w1, cpb_b1, cpb_w2);
    bias_expand_kernel<<<256, 256>>>();

    split_x_kernel<<<(MROWS * CHANS) / 1024, 256>>>(x);
    wsplit_kernel<<<(CHANS * QKVN + 255) / 256, 256>>>(
        w_qkv, (__nv_bfloat16*)p_wqh, (__nv_bfloat16*)p_wql, CHANS, QKVN);
    wsplit_kernel<<<(CHANS * CHANS + 255) / 256, 256>>>(
        proj_w, (__nv_bfloat16*)p_wph, (__nv_bfloat16*)p_wpl, CHANS, CHANS);

    // QKV: [131072,512] @ [512,1536]
    hmma_gemm<<<dim3(QKVN / 128, MROWS / 128), 256, GEMM_SMEM>>>(
        (const __nv_bfloat16*)p_xh, (const __nv_bfloat16*)p_xl,
        (const __nv_bfloat16*)p_wqh, (const __nv_bfloat16*)p_wql,
        (const float*)p_qb, (float*)p_qkv, MROWS, QKVN, CHANS);

    attn_kernel<<<dim3(NHEAD, BWIN), 256>>>(mask, lscale);

    // proj: [131072,512] @ [512,512]
    hmma_gemm<<<dim3(CHANS / 128, MROWS / 128), 256, GEMM_SMEM>>>(
        (const __nv_bfloat16*)p_aoh, (const __nv_bfloat16*)p_aol,
        (const __nv_bfloat16*)p_wph, (const __nv_bfloat16*)p_wpl,
        proj_b, out, MROWS, CHANS, CHANS);
}

// round 4
// speedup vs baseline: 1.6933x; 1.1101x over previous
#include <cuda_runtime.h>
#include <cuda_bf16.h>
#include <math.h>
#include <stdint.h>

// ---------------- problem constants ----------------
#define BWIN   2048
#define NTOK   64
#define CHANS  512
#define NHEAD  16
#define HDIM   32
#define NWMASK 256
#define MROWS  (BWIN * NTOK)     // 131072
#define QKVN   (3 * CHANS)       // 1536
#define LOGMAX 4.6051701859880914f

// ---------------- scratch ----------------
__device__ float g_qkv[(size_t)MROWS * QKVN];
__device__ __nv_bfloat16 g_x_hi[(size_t)MROWS * CHANS];
__device__ __nv_bfloat16 g_x_lo[(size_t)MROWS * CHANS];
__device__ __nv_bfloat16 g_ao_hi[(size_t)MROWS * CHANS];
__device__ __nv_bfloat16 g_ao_lo[(size_t)MROWS * CHANS];
__device__ __nv_bfloat16 g_wq_hi[(size_t)QKVN * CHANS];   // [N,K] transposed
__device__ __nv_bfloat16 g_wq_lo[(size_t)QKVN * CHANS];
__device__ __nv_bfloat16 g_wp_hi[(size_t)CHANS * CHANS];
__device__ __nv_bfloat16 g_wp_lo[(size_t)CHANS * CHANS];
__device__ float g_table[225 * NHEAD];
__device__ float g_bias[NHEAD * NTOK * NTOK];
__device__ float g_qkv_bias[QKVN];

// ---------------- helpers ----------------
__device__ __forceinline__ uint32_t smem_u32(const void* p) {
    uint32_t a;
    asm("{ .reg .u64 t; cvta.to.shared.u64 t, %1; cvt.u32.u64 %0, t; }" : "=r"(a) : "l"(p));
    return a;
}
__device__ __forceinline__ void cp16(uint32_t dst, const void* src) {
    asm volatile("cp.async.cg.shared.global [%0], [%1], 16;" :: "r"(dst), "l"(src));
}
#define CP_COMMIT() asm volatile("cp.async.commit_group;" ::: "memory")
__device__ __forceinline__ void cp_wait(int rem) {
    if (rem >= 1) asm volatile("cp.async.wait_group 1;" ::: "memory");
    else          asm volatile("cp.async.wait_group 0;" ::: "memory");
}
__device__ __forceinline__ void ldm_x4(uint32_t* r, uint32_t addr) {
    asm volatile("ldmatrix.sync.aligned.m8n8.x4.shared.b16 {%0,%1,%2,%3}, [%4];"
                 : "=r"(r[0]), "=r"(r[1]), "=r"(r[2]), "=r"(r[3]) : "r"(addr));
}
__device__ __forceinline__ void mma_bf16(float* d, const uint32_t* a, uint32_t b0, uint32_t b1) {
    asm volatile(
        "mma.sync.aligned.m16n8k16.row.col.f32.bf16.bf16.f32 "
        "{%0,%1,%2,%3}, {%4,%5,%6,%7}, {%8,%9}, {%0,%1,%2,%3};"
        : "+f"(d[0]), "+f"(d[1]), "+f"(d[2]), "+f"(d[3])
        : "r"(a[0]), "r"(a[1]), "r"(a[2]), "r"(a[3]), "r"(b0), "r"(b1));
}
__device__ __forceinline__ void split1(float x, __nv_bfloat16& h, __nv_bfloat16& l) {
    h = __float2bfloat16(x);
    l = __float2bfloat16(x - __bfloat162float(h));
}
// fast exp via FMA polynomial (no MUFU): exp(x) = 2^(x*log2e)
__device__ __forceinline__ float fexp(float x) {
    float t = fmaxf(x * 1.442695040888963f, -125.f);
    float n = rintf(t);
    float f = t - n;
    float p = 1.3392138e-3f;
    p = fmaf(p, f, 9.6181291e-3f);
    p = fmaf(p, f, 5.5504108e-2f);
    p = fmaf(p, f, 2.4022650e-1f);
    p = fmaf(p, f, 6.9314718e-1f);
    p = fmaf(p, f, 1.0f);
    return __int_as_float(((int)n + 127) << 23) * p;
}

// ---------------- tiny prep kernels ----------------
__global__ void qkvbias_kernel(const float* __restrict__ qb,
                               const float* __restrict__ vb) {
    int n = blockIdx.x * 256 + threadIdx.x;
    if (n >= QKVN) return;
    float v = 0.f;
    if (n < CHANS) v = qb[n];
    else if (n >= 2 * CHANS) v = vb[n - 2 * CHANS];
    g_qkv_bias[n] = v;
}

__global__ void cpb_table_kernel(const float* __restrict__ rel_table,
                                 const float* __restrict__ w1,
                                 const float* __restrict__ b1,
                                 const float* __restrict__ w2) {
    int p = blockIdx.x;
    int j = threadIdx.x;
    __shared__ float hid[512];
    float t0 = rel_table[p * 2 + 0];
    float t1 = rel_table[p * 2 + 1];
    hid[j] = fmaxf(t0 * w1[j] + t1 * w1[512 + j] + b1[j], 0.f);
    __syncthreads();
    if (j < NHEAD) {
        float acc = 0.f;
        #pragma unroll 8
        for (int r = 0; r < 512; ++r) acc += hid[r] * w2[r * NHEAD + j];
        g_table[p * NHEAD + j] = acc;
    }
}

__global__ void bias_expand_kernel() {
    int id = blockIdx.x * 256 + threadIdx.x;
    int h = id >> 12;
    int i = (id >> 6) & 63;
    int j = id & 63;
    int idx = ((i >> 3) - (j >> 3) + 7) * 15 + ((i & 7) - (j & 7) + 7);
    float b = g_table[idx * NHEAD + h];
    g_bias[id] = 16.f / (1.f + fexp(-b));
}

__global__ void split_x_kernel(const float* __restrict__ src) {
    size_t i = ((size_t)blockIdx.x * 256 + threadIdx.x) * 4;
    float4 v = *(const float4*)&src[i];
    __align__(8) __nv_bfloat16 h[4], l[4];
    split1(v.x, h[0], l[0]);
    split1(v.y, h[1], l[1]);
    split1(v.z, h[2], l[2]);
    split1(v.w, h[3], l[3]);
    *(uint2*)&g_x_hi[i] = *(uint2*)h;
    *(uint2*)&g_x_lo[i] = *(uint2*)l;
}

__global__ void wsplit_kernel(const float* __restrict__ w,
                              __nv_bfloat16* __restrict__ hiT,
                              __nv_bfloat16* __restrict__ loT,
                              int K, int N) {
    int idx = blockIdx.x * 256 + threadIdx.x;
    if (idx >= K * N) return;
    int k = idx / N, n = idx % N;
    __nv_bfloat16 h, l;
    split1(w[idx], h, l);
    hiT[(size_t)n * K + k] = h;
    loT[(size_t)n * K + k] = l;
}

// ---------------- HMMA bf16x3 GEMM ----------------
// C[M,N] = (Ahi+Alo)[M,K] @ (Bhi+Blo)[N,K]^T + bias[N]
// BM=128 BN=128 BK=32, 256 thr (8 warps 2Mx4N), warp tile 64x32,
// 2-stage cp.async pipeline (80KB smem -> 2 CTAs/SM).
#define PITCH 40
#define TILE_B (128 * PITCH * 2)         // 10240 B
#define STAGE_B (4 * TILE_B)
#define NSTAGE 2
#define GEMM_SMEM (NSTAGE * STAGE_B)     // 81920 B

__global__ void __launch_bounds__(256, 2)
hmma_gemm(const __nv_bfloat16* __restrict__ Ahi, const __nv_bfloat16* __restrict__ Alo,
          const __nv_bfloat16* __restrict__ Bhi, const __nv_bfloat16* __restrict__ Blo,
          const float* __restrict__ bias, float* __restrict__ C,
          int M, int N, int K) {
    extern __shared__ char smem[];
    const uint32_t sb = smem_u32(smem);
    const int tid = threadIdx.x;
    const int wid = tid >> 5, lane = tid & 31;
    const int bm = blockIdx.y * 128;
    const int bn = blockIdx.x * 128;
    const int wm = (wid >> 2) * 64;
    const int wn = (wid & 3) * 32;
    const int nch = K >> 5;

    auto load_tile = [&](const __nv_bfloat16* g, int rowbase, int k0, uint32_t off) {
        #pragma unroll
        for (int c = tid; c < 512; c += 256) {
            int row = c >> 2, chunk = c & 3;
            cp16(sb + off + row * (PITCH * 2) + chunk * 16,
                 g + (size_t)(rowbase + row) * K + k0 + chunk * 8);
        }
    };
    auto load_chunk = [&](int chunk) {
        int k0 = chunk << 5;
        uint32_t s0 = (uint32_t)(chunk & 1) * STAGE_B;
        load_tile(Ahi, bm, k0, s0);
        load_tile(Alo, bm, k0, s0 + TILE_B);
        load_tile(Bhi, bn, k0, s0 + 2 * TILE_B);
        load_tile(Blo, bn, k0, s0 + 3 * TILE_B);
        CP_COMMIT();
    };

    float acc[4][4][4] = {};

    load_chunk(0);

    const int lt = lane >> 3;
    const int lr = lane & 7;
    const int a_row_in = ((lt & 1) << 3) + lr;
    const int a_k16 = lt >> 1;
    const int b_n_in = ((lt >> 1) << 3) + lr;
    const int b_k16 = lt & 1;

    for (int i = 0; i < nch; ++i) {
        if (i + 1 < nch) load_chunk(i + 1);
        cp_wait(i + 1 < nch ? 1 : 0);
        __syncthreads();

        const uint32_t s0 = sb + (uint32_t)(i & 1) * STAGE_B;
        #pragma unroll
        for (int ks = 0; ks < 2; ++ks) {
            uint32_t afh[4][4], bfh[2][4], tf[4][4];
            #pragma unroll
            for (int mi = 0; mi < 4; ++mi)
                ldm_x4(afh[mi], s0 + (wm + mi * 16 + a_row_in) * (PITCH * 2)
                                 + ks * 32 + a_k16 * 16);
            #pragma unroll
            for (int ni = 0; ni < 2; ++ni)
                ldm_x4(bfh[ni], s0 + 2 * TILE_B
                                 + (wn + ni * 16 + b_n_in) * (PITCH * 2)
                                 + ks * 32 + b_k16 * 16);
            #pragma unroll
            for (int mi = 0; mi < 4; ++mi)
                #pragma unroll
                for (int nj = 0; nj < 4; ++nj)
                    mma_bf16(acc[mi][nj], afh[mi], bfh[nj >> 1][(nj & 1) * 2],
                             bfh[nj >> 1][(nj & 1) * 2 + 1]);
            #pragma unroll
            for (int ni = 0; ni < 2; ++ni)
                ldm_x4(tf[ni], s0 + 3 * TILE_B
                                + (wn + ni * 16 + b_n_in) * (PITCH * 2)
                                + ks * 32 + b_k16 * 16);
            #pragma unroll
            for (int mi = 0; mi < 4; ++mi)
                #pragma unroll
                for (int nj = 0; nj < 4; ++nj)
                    mma_bf16(acc[mi][nj], afh[mi], tf[nj >> 1][(nj & 1) * 2],
                             tf[nj >> 1][(nj & 1) * 2 + 1]);
            #pragma unroll
            for (int mi = 0; mi < 4; ++mi)
                ldm_x4(tf[mi], s0 + TILE_B + (wm + mi * 16 + a_row_in) * (PITCH * 2)
                                + ks * 32 + a_k16 * 16);
            #pragma unroll
            for (int mi = 0; mi < 4; ++mi)
                #pragma unroll
                for (int nj = 0; nj < 4; ++nj)
                    mma_bf16(acc[mi][nj], tf[mi], bfh[nj >> 1][(nj & 1) * 2],
                             bfh[nj >> 1][(nj & 1) * 2 + 1]);
        }
        __syncthreads();
    }

    const int er = lane >> 2;
    const int ec = (lane & 3) * 2;
    #pragma unroll
    for (int mi = 0; mi < 4; ++mi) {
        #pragma unroll
        for (int nj = 0; nj < 4; ++nj) {
            int col = bn + wn + nj * 8 + ec;
            float b0 = bias[col], b1 = bias[col + 1];
            int r0 = bm + wm + mi * 16 + er;
            float2 v0 = make_float2(acc[mi][nj][0] + b0, acc[mi][nj][1] + b1);
            float2 v1 = make_float2(acc[mi][nj][2] + b0, acc[mi][nj][3] + b1);
            *(float2*)&C[(size_t)r0 * N + col] = v0;
            *(float2*)&C[(size_t)(r0 + 8) * N + col] = v1;
        }
    }
}

// ---------------- attention: one CTA per (head, window) ------------------
__global__ __launch_bounds__(256)
void attn_kernel(const float* __restrict__ mask,
                 const float* __restrict__ logit_scale) {
    const int h = blockIdx.x;
    const int win = blockIdx.y;
    __shared__ float qs[64][32];
    __shared__ float ks[64][32];
    __shared__ float vs[64][32];
    __shared__ float S[64][65];
    const int tid = threadIdx.x;

    const size_t base = (size_t)win * 64 * QKVN + h * HDIM;
    #pragma unroll
    for (int l = 0; l < 2; ++l) {
        int t = tid + l * 256;
        int n = t >> 3;
        int f = (t & 7) << 2;
        const float* rowp = &g_qkv[base + (size_t)n * QKVN];
        *(float4*)&qs[n][f] = *(const float4*)&rowp[f];
        *(float4*)&ks[n][f] = *(const float4*)&rowp[512 + f];
        *(float4*)&vs[n][f] = *(const float4*)&rowp[1024 + f];
    }
    float scale = fexp(fminf(logit_scale[h], LOGMAX));
    __syncthreads();

    // L2-normalize: 2 lanes per row (lane pair shares via shfl), scale folded into q
    {
        int r = tid >> 1;                  // 0..127
        int half = tid & 1;
        float* row = (r < 64) ? qs[r] : ks[r - 64];
        float ss = 0.f;
        #pragma unroll
        for (int d4 = 0; d4 < 16; d4 += 4) {
            float4 v = *(float4*)&row[half * 16 + d4];
            ss += v.x * v.x + v.y * v.y + v.z * v.z + v.w * v.w;
        }
        ss += __shfl_xor_sync(0xffffffffu, ss, 1);
        float inv = rsqrtf(ss);
        if (r < 64) inv *= scale;
        #pragma unroll
        for (int d = 0; d < 16; ++d) row[half * 16 + d] *= inv;
    }
    __syncthreads();

    // S row i handled by quad of 4 lanes; 16 cols each; softmax via quad shuffles
    const int i = tid >> 2;
    const int j0 = (tid & 3) * 16;
    float q[32];
    #pragma unroll
    for (int d = 0; d < 32; ++d) q[d] = qs[i][d];
    const float* bias_h = &g_bias[h * 4096];
    const float* mask_w = &mask[(size_t)(win & (NWMASK - 1)) * 4096];
    float sv[16];
    #pragma unroll
    for (int jj = 0; jj < 16; ++jj) {
        int j = j0 + jj;
        float s = 0.f;
        #pragma unroll
        for (int d = 0; d < 32; ++d) s += q[d] * ks[j][d];
        sv[jj] = s + bias_h[i * 64 + j] + mask_w[i * 64 + j];
    }
    float m = -1e30f;
    #pragma unroll
    for (int jj = 0; jj < 16; ++jj) m = fmaxf(m, sv[jj]);
    m = fmaxf(m, __shfl_xor_sync(0xffffffffu, m, 1));
    m = fmaxf(m, __shfl_xor_sync(0xffffffffu, m, 2));
    float sum = 0.f;
    #pragma unroll
    for (int jj = 0; jj < 16; ++jj) {
        float e = fexp(sv[jj] - m);
        sv[jj] = e;
        sum += e;
    }
    sum += __shfl_xor_sync(0xffffffffu, sum, 1);
    sum += __shfl_xor_sync(0xffffffffu, sum, 2);
    float inv = __frcp_rn(sum);
    #pragma unroll
    for (int jj = 0; jj < 16; ++jj) S[i][j0 + jj] = sv[jj] * inv;
    __syncthreads();

    const int dd0 = (tid & 3) * 8;
    float acc[8] = {};
    #pragma unroll
    for (int j = 0; j < 64; ++j) {
        float p = S[i][j];
        #pragma unroll
        for (int u = 0; u < 8; ++u) acc[u] += p * vs[j][dd0 + u];
    }
    size_t orow = ((size_t)win * 64 + i) * CHANS + h * HDIM + dd0;
    __align__(16) __nv_bfloat16 hv[8], lv[8];
    #pragma unroll
    for (int u = 0; u < 8; ++u) split1(acc[u], hv[u], lv[u]);
    *(uint4*)&g_ao_hi[orow] = *(uint4*)hv;
    *(uint4*)&g_ao_lo[orow] = *(uint4*)lv;
}

// ---------------- launch ----------------
extern "C" void kernel_launch(void* const* d_in, const int* in_sizes, int n_in,
                              void* d_out, int out_size) {
    const float* x       = (const float*)d_in[0];
    const float* mask    = (const float*)d_in[1];
    const float* rel_t   = (const float*)d_in[2];
    const float* w_qkv   = (const float*)d_in[3];
    const float* q_bias  = (const float*)d_in[4];
    const float* v_bias  = (const float*)d_in[5];
    const float* lscale  = (const float*)d_in[6];
    const float* cpb_w1  = (const float*)d_in[7];
    const float* cpb_b1  = (const float*)d_in[8];
    const float* cpb_w2  = (const float*)d_in[9];
    const float* proj_w  = (const float*)d_in[10];
    const float* proj_b  = (const float*)d_in[11];
    float* out = (float*)d_out;

    void *p_qkv, *p_qb, *p_xh, *p_xl, *p_aoh, *p_aol, *p_wqh, *p_wql, *p_wph, *p_wpl;
    cudaGetSymbolAddress(&p_qkv, g_qkv);
    cudaGetSymbolAddress(&p_qb, g_qkv_bias);
    cudaGetSymbolAddress(&p_xh, g_x_hi);
    cudaGetSymbolAddress(&p_xl, g_x_lo);
    cudaGetSymbolAddress(&p_aoh, g_ao_hi);
    cudaGetSymbolAddress(&p_aol, g_ao_lo);
    cudaGetSymbolAddress(&p_wqh, g_wq_hi);
    cudaGetSymbolAddress(&p_wql, g_wq_lo);
    cudaGetSymbolAddress(&p_wph, g_wp_hi);
    cudaGetSymbolAddress(&p_wpl, g_wp_lo);

    cudaFuncSetAttribute(hmma_gemm, cudaFuncAttributeMaxDynamicSharedMemorySize, GEMM_SMEM);

    qkvbias_kernel<<<6, 256>>>(q_bias, v_bias);
    cpb_table_kernel<<<225, 512>>>(rel_t, cpb_w1, cpb_b1, cpb_w2);
    bias_expand_kernel<<<256, 256>>>();

    split_x_kernel<<<(MROWS * CHANS) / 1024, 256>>>(x);
    wsplit_kernel<<<(CHANS * QKVN + 255) / 256, 256>>>(
        w_qkv, (__nv_bfloat16*)p_wqh, (__nv_bfloat16*)p_wql, CHANS, QKVN);
    wsplit_kernel<<<(CHANS * CHANS + 255) / 256, 256>>>(
        proj_w, (__nv_bfloat16*)p_wph, (__nv_bfloat16*)p_wpl, CHANS, CHANS);

    hmma_gemm<<<dim3(QKVN / 128, MROWS / 128), 256, GEMM_SMEM>>>(
        (const __nv_bfloat16*)p_xh, (const __nv_bfloat16*)p_xl,
        (const __nv_bfloat16*)p_wqh, (const __nv_bfloat16*)p_wql,
        (const float*)p_qb, (float*)p_qkv, MROWS, QKVN, CHANS);

    attn_kernel<<<dim3(NHEAD, BWIN), 256>>>(mask, lscale);

    hmma_gemm<<<dim3(CHANS / 128, MROWS / 128), 256, GEMM_SMEM>>>(
        (const __nv_bfloat16*)p_aoh, (const __nv_bfloat16*)p_aol,
        (const __nv_bfloat16*)p_wph, (const __nv_bfloat16*)p_wpl,
        proj_b, out, MROWS, CHANS, CHANS);
}

// round 5
// speedup vs baseline: 3.0077x; 1.7762x over previous
#include <cuda_runtime.h>
#include <cuda_bf16.h>
#include <math.h>
#include <stdint.h>

// ---------------- problem constants ----------------
#define BWIN   2048
#define NTOK   64
#define CHANS  512
#define NHEAD  16
#define HDIM   32
#define NWMASK 256
#define MROWS  (BWIN * NTOK)     // 131072
#define QKVN   (3 * CHANS)       // 1536
#define LOGMAX 4.6051701859880914f

// ---------------- scratch ----------------
__device__ float g_qkv[(size_t)MROWS * QKVN];
__device__ __nv_bfloat16 g_x_hi[(size_t)MROWS * CHANS];
__device__ __nv_bfloat16 g_x_lo[(size_t)MROWS * CHANS];
__device__ __nv_bfloat16 g_ao_hi[(size_t)MROWS * CHANS];
__device__ __nv_bfloat16 g_ao_lo[(size_t)MROWS * CHANS];
__device__ __nv_bfloat16 g_wq_hi[(size_t)QKVN * CHANS];   // [N,K] transposed
__device__ __nv_bfloat16 g_wq_lo[(size_t)QKVN * CHANS];
__device__ __nv_bfloat16 g_wp_hi[(size_t)CHANS * CHANS];
__device__ __nv_bfloat16 g_wp_lo[(size_t)CHANS * CHANS];
__device__ float g_table[225 * NHEAD];
__device__ float g_bias[NHEAD * NTOK * NTOK];
__device__ float g_qkv_bias[QKVN];

// ---------------- helpers ----------------
__device__ __forceinline__ uint32_t smem_u32(const void* p) {
    uint32_t a;
    asm("{ .reg .u64 t; cvta.to.shared.u64 t, %1; cvt.u32.u64 %0, t; }" : "=r"(a) : "l"(p));
    return a;
}
__device__ __forceinline__ void cp16(uint32_t dst, const void* src) {
    asm volatile("cp.async.cg.shared.global [%0], [%1], 16;" :: "r"(dst), "l"(src));
}
#define CP_COMMIT() asm volatile("cp.async.commit_group;" ::: "memory")
__device__ __forceinline__ void cp_wait(int rem) {
    if (rem >= 1) asm volatile("cp.async.wait_group 1;" ::: "memory");
    else          asm volatile("cp.async.wait_group 0;" ::: "memory");
}
__device__ __forceinline__ void ldm_x4(uint32_t* r, uint32_t addr) {
    asm volatile("ldmatrix.sync.aligned.m8n8.x4.shared.b16 {%0,%1,%2,%3}, [%4];"
                 : "=r"(r[0]), "=r"(r[1]), "=r"(r[2]), "=r"(r[3]) : "r"(addr));
}
__device__ __forceinline__ void mma_bf16(float* d, const uint32_t* a, uint32_t b0, uint32_t b1) {
    asm volatile(
        "mma.sync.aligned.m16n8k16.row.col.f32.bf16.bf16.f32 "
        "{%0,%1,%2,%3}, {%4,%5,%6,%7}, {%8,%9}, {%0,%1,%2,%3};"
        : "+f"(d[0]), "+f"(d[1]), "+f"(d[2]), "+f"(d[3])
        : "r"(a[0]), "r"(a[1]), "r"(a[2]), "r"(a[3]), "r"(b0), "r"(b1));
}
__device__ __forceinline__ void split1(float x, __nv_bfloat16& h, __nv_bfloat16& l) {
    h = __float2bfloat16(x);
    l = __float2bfloat16(x - __bfloat162float(h));
}
// packed f32x2 FMA (Blackwell FFMA2, PTX-only)
__device__ __forceinline__ void ffma2(unsigned long long& d,
                                      unsigned long long a, unsigned long long b) {
    asm("fma.rn.f32x2 %0, %1, %2, %0;" : "+l"(d) : "l"(a), "l"(b));
}
__device__ __forceinline__ unsigned long long pack2(float x, float y) {
    unsigned long long r;
    asm("mov.b64 %0, {%1, %2};" : "=l"(r) : "f"(x), "f"(y));
    return r;
}
__device__ __forceinline__ void unpack2(unsigned long long v, float& x, float& y) {
    asm("mov.b64 {%0, %1}, %2;" : "=f"(x), "=f"(y) : "l"(v));
}
// fast exp via FMA polynomial (no MUFU)
__device__ __forceinline__ float fexp(float x) {
    float t = fmaxf(x * 1.442695040888963f, -125.f);
    float n = rintf(t);
    float f = t - n;
    float p = 1.3392138e-3f;
    p = fmaf(p, f, 9.6181291e-3f);
    p = fmaf(p, f, 5.5504108e-2f);
    p = fmaf(p, f, 2.4022650e-1f);
    p = fmaf(p, f, 6.9314718e-1f);
    p = fmaf(p, f, 1.0f);
    return __int_as_float(((int)n + 127) << 23) * p;
}

// ---------------- tiny prep kernels ----------------
__global__ void qkvbias_kernel(const float* __restrict__ qb,
                               const float* __restrict__ vb) {
    int n = blockIdx.x * 256 + threadIdx.x;
    if (n >= QKVN) return;
    float v = 0.f;
    if (n < CHANS) v = qb[n];
    else if (n >= 2 * CHANS) v = vb[n - 2 * CHANS];
    g_qkv_bias[n] = v;
}

__global__ void cpb_table_kernel(const float* __restrict__ rel_table,
                                 const float* __restrict__ w1,
                                 const float* __restrict__ b1,
                                 const float* __restrict__ w2) {
    int p = blockIdx.x;
    int j = threadIdx.x;
    __shared__ float hid[512];
    float t0 = rel_table[p * 2 + 0];
    float t1 = rel_table[p * 2 + 1];
    hid[j] = fmaxf(t0 * w1[j] + t1 * w1[512 + j] + b1[j], 0.f);
    __syncthreads();
    if (j < NHEAD) {
        float acc = 0.f;
        #pragma unroll 8
        for (int r = 0; r < 512; ++r) acc += hid[r] * w2[r * NHEAD + j];
        g_table[p * NHEAD + j] = acc;
    }
}

__global__ void bias_expand_kernel() {
    int id = blockIdx.x * 256 + threadIdx.x;
    int h = id >> 12;
    int i = (id >> 6) & 63;
    int j = id & 63;
    int idx = ((i >> 3) - (j >> 3) + 7) * 15 + ((i & 7) - (j & 7) + 7);
    float b = g_table[idx * NHEAD + h];
    g_bias[id] = 16.f / (1.f + fexp(-b));
}

__global__ void split_x_kernel(const float* __restrict__ src) {
    size_t i = ((size_t)blockIdx.x * 256 + threadIdx.x) * 4;
    float4 v = *(const float4*)&src[i];
    __align__(8) __nv_bfloat16 h[4], l[4];
    split1(v.x, h[0], l[0]);
    split1(v.y, h[1], l[1]);
    split1(v.z, h[2], l[2]);
    split1(v.w, h[3], l[3]);
    *(uint2*)&g_x_hi[i] = *(uint2*)h;
    *(uint2*)&g_x_lo[i] = *(uint2*)l;
}

__global__ void wsplit_kernel(const float* __restrict__ w,
                              __nv_bfloat16* __restrict__ hiT,
                              __nv_bfloat16* __restrict__ loT,
                              int K, int N) {
    int idx = blockIdx.x * 256 + threadIdx.x;
    if (idx >= K * N) return;
    int k = idx / N, n = idx % N;
    __nv_bfloat16 h, l;
    split1(w[idx], h, l);
    hiT[(size_t)n * K + k] = h;
    loT[(size_t)n * K + k] = l;
}

// ---------------- HMMA bf16x3 GEMM ----------------
#define PITCH 40
#define TILE_B (128 * PITCH * 2)
#define STAGE_B (4 * TILE_B)
#define NSTAGE 2
#define GEMM_SMEM (NSTAGE * STAGE_B)     // 81920 B

__global__ void __launch_bounds__(256, 2)
hmma_gemm(const __nv_bfloat16* __restrict__ Ahi, const __nv_bfloat16* __restrict__ Alo,
          const __nv_bfloat16* __restrict__ Bhi, const __nv_bfloat16* __restrict__ Blo,
          const float* __restrict__ bias, float* __restrict__ C,
          int M, int N, int K) {
    extern __shared__ char smem[];
    const uint32_t sb = smem_u32(smem);
    const int tid = threadIdx.x;
    const int wid = tid >> 5, lane = tid & 31;
    const int bm = blockIdx.y * 128;
    const int bn = blockIdx.x * 128;
    const int wm = (wid >> 2) * 64;
    const int wn = (wid & 3) * 32;
    const int nch = K >> 5;

    auto load_tile = [&](const __nv_bfloat16* g, int rowbase, int k0, uint32_t off) {
        #pragma unroll
        for (int c = tid; c < 512; c += 256) {
            int row = c >> 2, chunk = c & 3;
            cp16(sb + off + row * (PITCH * 2) + chunk * 16,
                 g + (size_t)(rowbase + row) * K + k0 + chunk * 8);
        }
    };
    auto load_chunk = [&](int chunk) {
        int k0 = chunk << 5;
        uint32_t s0 = (uint32_t)(chunk & 1) * STAGE_B;
        load_tile(Ahi, bm, k0, s0);
        load_tile(Alo, bm, k0, s0 + TILE_B);
        load_tile(Bhi, bn, k0, s0 + 2 * TILE_B);
        load_tile(Blo, bn, k0, s0 + 3 * TILE_B);
        CP_COMMIT();
    };

    float acc[4][4][4] = {};

    load_chunk(0);

    const int lt = lane >> 3;
    const int lr = lane & 7;
    const int a_row_in = ((lt & 1) << 3) + lr;
    const int a_k16 = lt >> 1;
    const int b_n_in = ((lt >> 1) << 3) + lr;
    const int b_k16 = lt & 1;

    for (int i = 0; i < nch; ++i) {
        if (i + 1 < nch) load_chunk(i + 1);
        cp_wait(i + 1 < nch ? 1 : 0);
        __syncthreads();

        const uint32_t s0 = sb + (uint32_t)(i & 1) * STAGE_B;
        #pragma unroll
        for (int ks = 0; ks < 2; ++ks) {
            uint32_t afh[4][4], bfh[2][4], tf[4][4];
            #pragma unroll
            for (int mi = 0; mi < 4; ++mi)
                ldm_x4(afh[mi], s0 + (wm + mi * 16 + a_row_in) * (PITCH * 2)
                                 + ks * 32 + a_k16 * 16);
            #pragma unroll
            for (int ni = 0; ni < 2; ++ni)
                ldm_x4(bfh[ni], s0 + 2 * TILE_B
                                 + (wn + ni * 16 + b_n_in) * (PITCH * 2)
                                 + ks * 32 + b_k16 * 16);
            #pragma unroll
            for (int mi = 0; mi < 4; ++mi)
                #pragma unroll
                for (int nj = 0; nj < 4; ++nj)
                    mma_bf16(acc[mi][nj], afh[mi], bfh[nj >> 1][(nj & 1) * 2],
                             bfh[nj >> 1][(nj & 1) * 2 + 1]);
            #pragma unroll
            for (int ni = 0; ni < 2; ++ni)
                ldm_x4(tf[ni], s0 + 3 * TILE_B
                                + (wn + ni * 16 + b_n_in) * (PITCH * 2)
                                + ks * 32 + b_k16 * 16);
            #pragma unroll
            for (int mi = 0; mi < 4; ++mi)
                #pragma unroll
                for (int nj = 0; nj < 4; ++nj)
                    mma_bf16(acc[mi][nj], afh[mi], tf[nj >> 1][(nj & 1) * 2],
                             tf[nj >> 1][(nj & 1) * 2 + 1]);
            #pragma unroll
            for (int mi = 0; mi < 4; ++mi)
                ldm_x4(tf[mi], s0 + TILE_B + (wm + mi * 16 + a_row_in) * (PITCH * 2)
                                + ks * 32 + a_k16 * 16);
            #pragma unroll
            for (int mi = 0; mi < 4; ++mi)
                #pragma unroll
                for (int nj = 0; nj < 4; ++nj)
                    mma_bf16(acc[mi][nj], tf[mi], bfh[nj >> 1][(nj & 1) * 2],
                             bfh[nj >> 1][(nj & 1) * 2 + 1]);
        }
        __syncthreads();
    }

    const int er = lane >> 2;
    const int ec = (lane & 3) * 2;
    #pragma unroll
    for (int mi = 0; mi < 4; ++mi) {
        #pragma unroll
        for (int nj = 0; nj < 4; ++nj) {
            int col = bn + wn + nj * 8 + ec;
            float b0 = bias[col], b1 = bias[col + 1];
            int r0 = bm + wm + mi * 16 + er;
            float2 v0 = make_float2(acc[mi][nj][0] + b0, acc[mi][nj][1] + b1);
            float2 v1 = make_float2(acc[mi][nj][2] + b0, acc[mi][nj][3] + b1);
            *(float2*)&C[(size_t)r0 * N + col] = v0;
            *(float2*)&C[(size_t)(r0 + 8) * N + col] = v1;
        }
    }
}

// ---------------- attention v2: blocked f32x2, one CTA per (head, window) --
#define QKP 34   // row stride (floats) for q/k/v smem
__global__ __launch_bounds__(256)
void attn_kernel(const float* __restrict__ mask,
                 const float* __restrict__ logit_scale) {
    const int h = blockIdx.x;
    const int win = blockIdx.y;
    __shared__ float qs[64][QKP];
    __shared__ float ks[64][QKP];
    __shared__ float vs[64][QKP];
    __shared__ float S[64][65];
    const int tid = threadIdx.x;

    // load q,k,v (float2 stores: QKP rows are 8B aligned)
    const size_t base = (size_t)win * 64 * QKVN + h * HDIM;
    #pragma unroll
    for (int l = 0; l < 2; ++l) {
        int t = tid + l * 256;
        int n = t >> 3;
        int f = (t & 7) << 2;
        const float* rowp = &g_qkv[base + (size_t)n * QKVN];
        float4 qv = *(const float4*)&rowp[f];
        float4 kv = *(const float4*)&rowp[512 + f];
        float4 vv = *(const float4*)&rowp[1024 + f];
        *(float2*)&qs[n][f]     = make_float2(qv.x, qv.y);
        *(float2*)&qs[n][f + 2] = make_float2(qv.z, qv.w);
        *(float2*)&ks[n][f]     = make_float2(kv.x, kv.y);
        *(float2*)&ks[n][f + 2] = make_float2(kv.z, kv.w);
        *(float2*)&vs[n][f]     = make_float2(vv.x, vv.y);
        *(float2*)&vs[n][f + 2] = make_float2(vv.z, vv.w);
    }
    float scale = fexp(fminf(logit_scale[h], LOGMAX));
    __syncthreads();

    // L2-normalize: 2 lanes per row, scale folded into q
    {
        int r = tid >> 1;
        int half = tid & 1;
        float* row = (r < 64) ? qs[r] : ks[r - 64];
        float ss = 0.f;
        #pragma unroll
        for (int d2 = 0; d2 < 16; d2 += 2) {
            float2 v = *(float2*)&row[half * 16 + d2];
            ss += v.x * v.x + v.y * v.y;
        }
        ss += __shfl_xor_sync(0xffffffffu, ss, 1);
        float inv = rsqrtf(ss);
        if (r < 64) inv *= scale;
        #pragma unroll
        for (int d = 0; d < 16; ++d) row[half * 16 + d] *= inv;
    }
    __syncthreads();

    // QK: thread (ty,tx) computes 4x4 block: rows 4ty+ii, cols tx+16jj
    const int ty = tid >> 4, tx = tid & 15;
    unsigned long long a2[4][4];
    #pragma unroll
    for (int ii = 0; ii < 4; ++ii)
        #pragma unroll
        for (int jj = 0; jj < 4; ++jj) a2[ii][jj] = 0ull;
    #pragma unroll
    for (int d2 = 0; d2 < 16; ++d2) {
        unsigned long long q2[4], k2[4];
        #pragma unroll
        for (int ii = 0; ii < 4; ++ii)
            q2[ii] = *(unsigned long long*)&qs[4 * ty + ii][2 * d2];
        #pragma unroll
        for (int jj = 0; jj < 4; ++jj)
            k2[jj] = *(unsigned long long*)&ks[tx + 16 * jj][2 * d2];
        #pragma unroll
        for (int ii = 0; ii < 4; ++ii)
            #pragma unroll
            for (int jj = 0; jj < 4; ++jj)
                ffma2(a2[ii][jj], q2[ii], k2[jj]);
    }
    const float* bias_h = &g_bias[h * 4096];
    const float* mask_w = &mask[(size_t)(win & (NWMASK - 1)) * 4096];
    float sv[4][4];
    #pragma unroll
    for (int ii = 0; ii < 4; ++ii) {
        int r = 4 * ty + ii;
        #pragma unroll
        for (int jj = 0; jj < 4; ++jj) {
            int c = tx + 16 * jj;
            float x, y;
            unpack2(a2[ii][jj], x, y);
            sv[ii][jj] = x + y + bias_h[r * 64 + c] + mask_w[r * 64 + c];
        }
    }
    // row softmax: reduce over tx (16 lanes, xor 1,2,4,8)
    float mr[4], sr[4];
    #pragma unroll
    for (int ii = 0; ii < 4; ++ii) {
        float m = fmaxf(fmaxf(sv[ii][0], sv[ii][1]), fmaxf(sv[ii][2], sv[ii][3]));
        m = fmaxf(m, __shfl_xor_sync(0xffffffffu, m, 1));
        m = fmaxf(m, __shfl_xor_sync(0xffffffffu, m, 2));
        m = fmaxf(m, __shfl_xor_sync(0xffffffffu, m, 4));
        m = fmaxf(m, __shfl_xor_sync(0xffffffffu, m, 8));
        mr[ii] = m;
        float s = 0.f;
        #pragma unroll
        for (int jj = 0; jj < 4; ++jj) {
            sv[ii][jj] = fexp(sv[ii][jj] - m);
            s += sv[ii][jj];
        }
        s += __shfl_xor_sync(0xffffffffu, s, 1);
        s += __shfl_xor_sync(0xffffffffu, s, 2);
        s += __shfl_xor_sync(0xffffffffu, s, 4);
        s += __shfl_xor_sync(0xffffffffu, s, 8);
        sr[ii] = __frcp_rn(s);
    }
    #pragma unroll
    for (int ii = 0; ii < 4; ++ii)
        #pragma unroll
        for (int jj = 0; jj < 4; ++jj)
            S[4 * ty + ii][tx + 16 * jj] = sv[ii][jj] * sr[ii];
    __syncthreads();

    // PV: thread (ti,tu): rows 4ti+ii, dims (2tu, 2tu+1)
    const int ti = ty, tu = tx;
    unsigned long long pa[4] = {0ull, 0ull, 0ull, 0ull};
    #pragma unroll 4
    for (int j = 0; j < 64; ++j) {
        unsigned long long v2 = *(unsigned long long*)&vs[j][2 * tu];
        #pragma unroll
        for (int ii = 0; ii < 4; ++ii) {
            float p = S[4 * ti + ii][j];
            ffma2(pa[ii], pack2(p, p), v2);
        }
    }
    #pragma unroll
    for (int ii = 0; ii < 4; ++ii) {
        float x, y;
        unpack2(pa[ii], x, y);
        size_t orow = ((size_t)win * 64 + 4 * ti + ii) * CHANS + h * HDIM + 2 * tu;
        __nv_bfloat16 hx, lx, hy, ly;
        split1(x, hx, lx);
        split1(y, hy, ly);
        __nv_bfloat162 hv, lv;
        hv.x = hx; hv.y = hy;
        lv.x = lx; lv.y = ly;
        *(__nv_bfloat162*)&g_ao_hi[orow] = hv;
        *(__nv_bfloat162*)&g_ao_lo[orow] = lv;
    }
    (void)mr;
}

// ---------------- launch ----------------
extern "C" void kernel_launch(void* const* d_in, const int* in_sizes, int n_in,
                              void* d_out, int out_size) {
    const float* x       = (const float*)d_in[0];
    const float* mask    = (const float*)d_in[1];
    const float* rel_t   = (const float*)d_in[2];
    const float* w_qkv   = (const float*)d_in[3];
    const float* q_bias  = (const float*)d_in[4];
    const float* v_bias  = (const float*)d_in[5];
    const float* lscale  = (const float*)d_in[6];
    const float* cpb_w1  = (const float*)d_in[7];
    const float* cpb_b1  = (const float*)d_in[8];
    const float* cpb_w2  = (const float*)d_in[9];
    const float* proj_w  = (const float*)d_in[10];
    const float* proj_b  = (const float*)d_in[11];
    float* out = (float*)d_out;

    void *p_qkv, *p_qb, *p_xh, *p_xl, *p_aoh, *p_aol, *p_wqh, *p_wql, *p_wph, *p_wpl;
    cudaGetSymbolAddress(&p_qkv, g_qkv);
    cudaGetSymbolAddress(&p_qb, g_qkv_bias);
    cudaGetSymbolAddress(&p_xh, g_x_hi);
    cudaGetSymbolAddress(&p_xl, g_x_lo);
    cudaGetSymbolAddress(&p_aoh, g_ao_hi);
    cudaGetSymbolAddress(&p_aol, g_ao_lo);
    cudaGetSymbolAddress(&p_wqh, g_wq_hi);
    cudaGetSymbolAddress(&p_wql, g_wq_lo);
    cudaGetSymbolAddress(&p_wph, g_wp_hi);
    cudaGetSymbolAddress(&p_wpl, g_wp_lo);

    cudaFuncSetAttribute(hmma_gemm, cudaFuncAttributeMaxDynamicSharedMemorySize, GEMM_SMEM);

    qkvbias_kernel<<<6, 256>>>(q_bias, v_bias);
    cpb_table_kernel<<<225, 512>>>(rel_t, cpb_w1, cpb_b1, cpb_w2);
    bias_expand_kernel<<<256, 256>>>();

    split_x_kernel<<<(MROWS * CHANS) / 1024, 256>>>(x);
    wsplit_kernel<<<(CHANS * QKVN + 255) / 256, 256>>>(
        w_qkv, (__nv_bfloat16*)p_wqh, (__nv_bfloat16*)p_wql, CHANS, QKVN);
    wsplit_kernel<<<(CHANS * CHANS + 255) / 256, 256>>>(
        proj_w, (__nv_bfloat16*)p_wph, (__nv_bfloat16*)p_wpl, CHANS, CHANS);

    hmma_gemm<<<dim3(QKVN / 128, MROWS / 128), 256, GEMM_SMEM>>>(
        (const __nv_bfloat16*)p_xh, (const __nv_bfloat16*)p_xl,
        (const __nv_bfloat16*)p_wqh, (const __nv_bfloat16*)p_wql,
        (const float*)p_qb, (float*)p_qkv, MROWS, QKVN, CHANS);

    attn_kernel<<<dim3(NHEAD, BWIN), 256>>>(mask, lscale);

    hmma_gemm<<<dim3(CHANS / 128, MROWS / 128), 256, GEMM_SMEM>>>(
        (const __nv_bfloat16*)p_aoh, (const __nv_bfloat16*)p_aol,
        (const __nv_bfloat16*)p_wph, (const __nv_bfloat16*)p_wpl,
        proj_b, out, MROWS, CHANS, CHANS);
}